// round 16
// baseline (speedup 1.0000x reference)
#include <cuda_runtime.h>
#include <math.h>

#define BB 4
#define NN 2048
#define MM 16
#define SS 200
#define PTS 512             // points per producer block
#define CHUNKS (NN / PTS)   // 4

#define PROD_WORK    (BB * MM * CHUNKS)        // 256 merged work blocks
#define PROD_BLOCKS  (PROD_WORK + 1)           // +1 emb block = 257
#define TAIL_P2P     32                        // 32 blocks x 256 points
#define TAIL_PRIM    (BB * MM)                 // 64 blocks, one per (b,m)
#define TAIL_BLOCKS  (TAIL_P2P + TAIL_PRIM)    // 96
#define GRID_BLOCKS  (PROD_BLOCKS + TAIL_BLOCKS)  // 353
#define FIN_COUNT    (TAIL_BLOCKS + 1)         // tails + emb block

typedef unsigned long long ull;

// ---------------- device scratch ----------------
__device__ float    g_dv[BB * NN * MM];                 // TRANSPOSED: [(b*NN+n)*MM + m]
__device__ float    g_dpart[BB * MM * CHUNKS * SS];     // per-chunk partial min-over-n
__device__ double   g_part[TAIL_BLOCKS];                // per-tail-block partial sums
__device__ double   g_emb;
__device__ unsigned g_cntP[BB * CHUNKS];                // per-(b,chunk) producer counters
__device__ unsigned g_cntB[BB * MM];                    // per-blkm producer counters
__device__ unsigned g_cnt2;                             // finisher ticket (self-resetting)

// ---------------- f32x2 packed helpers (sm_100) ----------------
__device__ __forceinline__ ull pk2(float lo, float hi) {
    ull r; asm("mov.b64 %0, {%1, %2};" : "=l"(r) : "f"(lo), "f"(hi)); return r;
}
__device__ __forceinline__ ull fma2(ull a, ull b, ull c) {
    ull r; asm("fma.rn.f32x2 %0, %1, %2, %3;" : "=l"(r) : "l"(a), "l"(b), "l"(c)); return r;
}
__device__ __forceinline__ void upk2(ull v, float& lo, float& hi) {
    asm("mov.b64 {%0, %1}, %2;" : "=f"(lo), "=f"(hi) : "l"(v));
}

__device__ __forceinline__ float fexp_f(float x, float p) {
    float s = (x > 0.f) ? 1.f : ((x < 0.f) ? -1.f : 0.f);
    return s * powf(fabsf(x) + 1e-6f, p);
}

__device__ __forceinline__ double blockReduceSumD(double v) {
    __shared__ double sh[32];
    int lane = threadIdx.x & 31, wid = threadIdx.x >> 5;
    #pragma unroll
    for (int o = 16; o; o >>= 1) v += __shfl_down_sync(0xffffffffu, v, o);
    if (lane == 0) sh[wid] = v;
    __syncthreads();
    int nw = (blockDim.x + 31) >> 5;
    v = (threadIdx.x < nw) ? sh[threadIdx.x] : 0.0;
    if (wid == 0) {
        #pragma unroll
        for (int o = 16; o; o >>= 1) v += __shfl_down_sync(0xffffffffu, v, o);
    }
    __syncthreads();
    return v;
}

// argmax_i emb[b][i][m]  (first max on ties)
__device__ __forceinline__ int argmax_col(const float* __restrict__ emb, int b, int m) {
    int j = 0;
    float best = emb[(b * MM + 0) * MM + m];
    #pragma unroll
    for (int i = 1; i < MM; i++) {
        float v = emb[(b * MM + i) * MM + m];
        if (v > best) { best = v; j = i; }
    }
    return j;
}

__device__ __forceinline__ void spin_until(volatile unsigned* c, unsigned target) {
    while (*c < target) __nanosleep(64);
}

// ---------------- THE kernel ----------------
__global__ void __launch_bounds__(256, 4) k_all(const float* __restrict__ pcl,
                                                const float* __restrict__ trans,
                                                const float* __restrict__ rot,
                                                const float* __restrict__ size,
                                                const float* __restrict__ shape,
                                                const float* __restrict__ deform,
                                                const float* __restrict__ prob,
                                                const float* __restrict__ emb,
                                                float* __restrict__ out)
{
    int bid = blockIdx.x, t = threadIdx.x;

    // ===================== PRODUCER BLOCKS =====================
    if (bid < PROD_BLOCKS) {
        if (bid == PROD_WORK) {
            // ---- embeddings regularizer ----
            double c1 = 0.0, c2 = 0.0, c3 = 0.0;
            if (t < BB * MM) {
                int bb = t / MM, k = t % MM;
                float s1 = 0.f, s2 = 0.f;
                for (int i = 0; i < MM; i++) {
                    s1 += emb[(bb * MM + i) * MM + k];
                    s2 += emb[(bb * MM + k) * MM + i];
                }
                float d1 = s1 - 1.f, d2 = s2 - 1.f;
                c1 = (double)(d1 * d1);
                c2 = (double)(d2 * d2);
            }
            for (int i = t; i < BB * MM * MM; i += 256) {
                float v = emb[i];
                c3 += (double)(v * (1.f - v));
            }
            double r1 = blockReduceSumD(c1);
            double r2 = blockReduceSumD(c2);
            double r3 = blockReduceSumD(c3);
            if (t == 0) {
                g_emb = r1 / (double)(BB * MM) + 10.0 * r2 / (double)(BB * MM)
                      + r3 / (double)(BB * MM * MM);
                __threadfence();
                atomicAdd(&g_cnt2, 1u);   // joins finisher count
            }
            return;
        }

        // merged work block: both distance loops for (blkm, chunk of 512 points)
        __shared__ ulonglong2 s_qA[SS / 2], s_qB[SS / 2];     // samples, packed pairs
        __shared__ ulonglong2 s_uA[PTS / 2], s_uB[PTS / 2];   // transformed points, packed
        __shared__ float  s_R[9], s_t[3], s_par[7];

        int blkm  = bid / CHUNKS;
        int chunk = bid % CHUNKS;
        int b     = blkm / MM, m = blkm % MM;

        if (t == 0) {
            int j = argmax_col(emb, b, m);
            const float* q = rot + blkm * 4;
            float w = q[0], x = q[1], y = q[2], z = q[3];
            float inv = rsqrtf(w * w + x * x + y * y + z * z);
            w *= inv; x *= inv; y *= inv; z *= inv;
            s_R[0] = 1.f - 2.f * (y * y + z * z); s_R[1] = 2.f * (x * y - w * z); s_R[2] = 2.f * (x * z + w * y);
            s_R[3] = 2.f * (x * y + w * z); s_R[4] = 1.f - 2.f * (x * x + z * z); s_R[5] = 2.f * (y * z - w * x);
            s_R[6] = 2.f * (x * z - w * y); s_R[7] = 2.f * (y * z + w * x); s_R[8] = 1.f - 2.f * (x * x + y * y);
            s_t[0] = trans[blkm * 3 + 0]; s_t[1] = trans[blkm * 3 + 1]; s_t[2] = trans[blkm * 3 + 2];
            const float* sz3 = size   + (b * MM + j) * 3;
            const float* sh2 = shape  + (b * MM + j) * 2;
            const float* df2 = deform + (b * MM + j) * 2;
            s_par[0] = sh2[0]; s_par[1] = sh2[1];
            s_par[2] = sz3[0]; s_par[3] = sz3[1]; s_par[4] = sz3[2];
            s_par[5] = df2[0]; s_par[6] = df2[1];
        }
        __syncthreads();

        // sample points -> packed smem (t < SS)
        if (t < SS) {
            float e1 = s_par[0], e2 = s_par[1];
            float sx = s_par[2], sy = s_par[3], szv = s_par[4];
            float dfx = s_par[5], dfy = s_par[6];
            double stepE = (M_PI - 0.1) / (double)(SS - 1);
            double stepO = (2.0 * M_PI - 0.1) / (double)(SS - 1);
            float eta = (float)(-M_PI / 2.0 + 0.05 + t * stepE);
            float omg = (float)(-M_PI + 0.05 + t * stepO);
            float ce = cosf(eta), se = sinf(eta), co = cosf(omg), so = sinf(omg);
            float fce = fexp_f(ce, e1);
            float x = sx * fce * fexp_f(co, e2);
            float y = sy * fce * fexp_f(so, e2);
            float z = szv * fexp_f(se, e1);
            float fx = dfx / szv * z + 1.f;
            float fy = dfy / szv * z + 1.f;
            float X = x * fx, Y = y * fy, Z = z;
            float W = fmaf(X, X, fmaf(Y, Y, Z * Z));
            int p = t >> 1, h = t & 1;
            float* A = (float*)s_qA;  float* Bf = (float*)s_qB;
            A[4 * p + h]     = X;  A[4 * p + 2 + h] = Y;
            Bf[4 * p + h]    = Z;  Bf[4 * p + 2 + h] = W;
        }

        // transform TWO points per thread (local l0 = t, l1 = t + 256)
        float R0 = s_R[0], R1 = s_R[1], R2 = s_R[2];
        float R3 = s_R[3], R4 = s_R[4], R5 = s_R[5];
        float R6 = s_R[6], R7 = s_R[7], R8 = s_R[8];
        float ux0, uy0, uz0, uw0, ux1, uy1, uz1, uw1;
        {
            int n0 = chunk * PTS + t;
            const float* P0 = pcl + (b * NN + n0) * 3;
            float ax = P0[0] - s_t[0], ay = P0[1] - s_t[1], az = P0[2] - s_t[2];
            ux0 = R0 * ax + R1 * ay + R2 * az;
            uy0 = R3 * ax + R4 * ay + R5 * az;
            uz0 = R6 * ax + R7 * ay + R8 * az;
            uw0 = fmaf(ux0, ux0, fmaf(uy0, uy0, uz0 * uz0));
            const float* P1 = P0 + 256 * 3;
            float bx = P1[0] - s_t[0], by = P1[1] - s_t[1], bz = P1[2] - s_t[2];
            ux1 = R0 * bx + R1 * by + R2 * bz;
            uy1 = R3 * bx + R4 * by + R5 * bz;
            uz1 = R6 * bx + R7 * by + R8 * bz;
            uw1 = fmaf(ux1, ux1, fmaf(uy1, uy1, uz1 * uz1));
            int p = t >> 1, h = t & 1;
            float* A = (float*)s_uA;  float* Bf = (float*)s_uB;
            A[4 * p + h]          = ux0; A[4 * p + 2 + h]        = uy0;
            Bf[4 * p + h]         = uz0; Bf[4 * p + 2 + h]       = uw0;
            A[4 * (p + 128) + h]  = ux1; A[4 * (p + 128) + 2 + h] = uy1;
            Bf[4 * (p + 128) + h] = uz1; Bf[4 * (p + 128) + 2 + h] = uw1;
        }
        __syncthreads();

        // ---------- p2p: min over S for BOTH points (each LDS feeds 2 points) ----------
        {
            ull x0p = pk2(-2.f * ux0, -2.f * ux0);
            ull y0p = pk2(-2.f * uy0, -2.f * uy0);
            ull z0p = pk2(-2.f * uz0, -2.f * uz0);
            ull x1p = pk2(-2.f * ux1, -2.f * ux1);
            ull y1p = pk2(-2.f * uy1, -2.f * uy1);
            ull z1p = pk2(-2.f * uz1, -2.f * uz1);

            float m00 = 3.4e38f, m01 = m00, m02 = m00, m03 = m00;
            float m10 = m00, m11 = m00, m12 = m00, m13 = m00;
            #pragma unroll 5
            for (int p = 0; p < SS / 2; p += 2) {
                ulonglong2 la0 = s_qA[p],     lb0 = s_qB[p];
                ulonglong2 la1 = s_qA[p + 1], lb1 = s_qB[p + 1];
                ull v; float lo, hi;
                v = fma2(la0.x, x0p, fma2(la0.y, y0p, fma2(lb0.x, z0p, lb0.y)));
                upk2(v, lo, hi); m00 = fminf(m00, lo); m01 = fminf(m01, hi);
                v = fma2(la0.x, x1p, fma2(la0.y, y1p, fma2(lb0.x, z1p, lb0.y)));
                upk2(v, lo, hi); m10 = fminf(m10, lo); m11 = fminf(m11, hi);
                v = fma2(la1.x, x0p, fma2(la1.y, y0p, fma2(lb1.x, z0p, lb1.y)));
                upk2(v, lo, hi); m02 = fminf(m02, lo); m03 = fminf(m03, hi);
                v = fma2(la1.x, x1p, fma2(la1.y, y1p, fma2(lb1.x, z1p, lb1.y)));
                upk2(v, lo, hi); m12 = fminf(m12, lo); m13 = fminf(m13, hi);
            }
            int n0 = chunk * PTS + t;
            float d0 = fminf(fminf(m00, m01), fminf(m02, m03)) + uw0;
            float d1 = fminf(fminf(m10, m11), fminf(m12, m13)) + uw1;
            d0 = fmaxf(d0, 0.f);
            d1 = fmaxf(d1, 0.f);
            g_dv[(b * NN + n0) * MM + m]       = d0;
            g_dv[(b * NN + n0 + 256) * MM + m] = d1;
        }

        // ---------- prim: 100 threads x 2 samples over 512 points ----------
        if (t < SS / 2) {
            int p0 = t >> 1, h0 = t & 1;          // sample s0 = t
            int p1 = p0 + 50;                     // sample s1 = t + 100 (same parity)
            const float* A = (const float*)s_qA;  const float* Bf = (const float*)s_qB;
            float qx0 = A[4 * p0 + h0], qy0 = A[4 * p0 + 2 + h0];
            float qz0 = Bf[4 * p0 + h0], qw0 = Bf[4 * p0 + 2 + h0];
            float qx1 = A[4 * p1 + h0], qy1 = A[4 * p1 + 2 + h0];
            float qz1 = Bf[4 * p1 + h0], qw1 = Bf[4 * p1 + 2 + h0];
            ull x0p = pk2(-2.f * qx0, -2.f * qx0);
            ull y0p = pk2(-2.f * qy0, -2.f * qy0);
            ull z0p = pk2(-2.f * qz0, -2.f * qz0);
            ull x1p = pk2(-2.f * qx1, -2.f * qx1);
            ull y1p = pk2(-2.f * qy1, -2.f * qy1);
            ull z1p = pk2(-2.f * qz1, -2.f * qz1);

            float a0 = 3.4e38f, a1 = a0, a2 = a0, a3 = a0;   // s0
            float c0 = a0, c1 = a0, c2 = a0, c3 = a0;        // s1
            #pragma unroll 4
            for (int p = 0; p < PTS / 2; p += 2) {
                ulonglong2 la0 = s_uA[p],     lb0 = s_uB[p];
                ulonglong2 la1 = s_uA[p + 1], lb1 = s_uB[p + 1];
                ull v; float lo, hi;
                v = fma2(la0.x, x0p, fma2(la0.y, y0p, fma2(lb0.x, z0p, lb0.y)));
                upk2(v, lo, hi); a0 = fminf(a0, lo); a1 = fminf(a1, hi);
                v = fma2(la0.x, x1p, fma2(la0.y, y1p, fma2(lb0.x, z1p, lb0.y)));
                upk2(v, lo, hi); c0 = fminf(c0, lo); c1 = fminf(c1, hi);
                v = fma2(la1.x, x0p, fma2(la1.y, y0p, fma2(lb1.x, z0p, lb1.y)));
                upk2(v, lo, hi); a2 = fminf(a2, lo); a3 = fminf(a3, hi);
                v = fma2(la1.x, x1p, fma2(la1.y, y1p, fma2(lb1.x, z1p, lb1.y)));
                upk2(v, lo, hi); c2 = fminf(c2, lo); c3 = fminf(c3, hi);
            }
            float d0 = fminf(fminf(a0, a1), fminf(a2, a3)) + qw0;
            float d1 = fminf(fminf(c0, c1), fminf(c2, c3)) + qw1;
            d0 = fmaxf(d0, 0.f);
            d1 = fmaxf(d1, 0.f);
            float* dst = g_dpart + (blkm * CHUNKS + chunk) * SS;
            dst[t]       = d0;
            dst[t + 100] = d1;
        }

        __syncthreads();
        if (t == 0) {
            __threadfence();
            atomicAdd(&g_cntP[b * CHUNKS + chunk], 1u);   // release for tail p2p
            atomicAdd(&g_cntB[blkm], 1u);                 // release for tail prim
        }
        return;
    }

    // ===================== TAIL BLOCKS (fine-grained waits) =====================
    int pid = bid - PROD_BLOCKS;   // 0..95
    double part = 0.0;

    if (pid < TAIL_P2P) {
        // ---- p2p weighting: 32 blocks x 256 points ----
        __shared__ float s_p[MM];
        int b = pid / 8, c8 = pid % 8;
        if (t < MM) s_p[t] = prob[b * MM + t];

        // wait only for this chunk's 16 m-producers
        if (t == 0) spin_until(&g_cntP[b * CHUNKS + (c8 >> 1)], MM);
        __syncthreads();
        __threadfence();

        int n = c8 * 256 + t;
        const float4* dvp = (const float4*)&g_dv[(b * NN + n) * MM];
        float dv[MM], pv[MM];
        float4 d0 = __ldcg(&dvp[0]), d1 = __ldcg(&dvp[1]);
        float4 d2 = __ldcg(&dvp[2]), d3 = __ldcg(&dvp[3]);
        ((float4*)dv)[0] = d0; ((float4*)dv)[1] = d1;
        ((float4*)dv)[2] = d2; ((float4*)dv)[3] = d3;
        #pragma unroll
        for (int mm = 0; mm < MM; mm++) pv[mm] = s_p[mm];

        float acc = 0.f;
        #pragma unroll
        for (int mm = 0; mm < MM; mm++) {
            float w = pv[mm];
            #pragma unroll
            for (int j = 0; j < MM; j++) {
                if (j == mm) continue;
                bool before = (dv[j] < dv[mm]) || (dv[j] == dv[mm] && j < mm);
                w *= before ? (1.f - pv[j]) : 1.f;
            }
            acc = fmaf(dv[mm], w, acc);
        }
        part = blockReduceSumD((double)acc) / (double)(BB * NN);
    } else {
        // ---- prim reduction: one block per (b,m) ----
        int blkm = pid - TAIL_P2P;
        int b = blkm / MM;
        __shared__ float s_a[MM];
        __shared__ float s_w[1];

        if (t < MM) {
            int j = argmax_col(emb, b, t);
            const float* sz3 = size + (b * MM + j) * 3;
            float a0 = sz3[0], a1 = sz3[1], a2 = sz3[2];
            float ar = powf(a0 * a1, 1.6f) / 3.f + powf(a0 * a2, 1.6f) / 3.f + powf(a1 * a2, 1.6f) / 3.f;
            s_a[t] = 4.f * (float)M_PI * powf(ar, 0.625f);
        }
        __syncthreads();
        if (t == 0) {
            float sa = 0.f;
            #pragma unroll
            for (int mm = 0; mm < MM; mm++) sa += s_a[mm];
            s_w[0] = s_a[blkm % MM] / sa / (float)(SS * BB);
        }

        // wait only for this blkm's 4 chunk-producers
        if (t == 0) spin_until(&g_cntB[blkm], CHUNKS);
        __syncthreads();
        __threadfence();
        float w = s_w[0];

        double acc = 0.0;
        if (t < SS) {
            const float* base = g_dpart + (blkm * CHUNKS) * SS + t;
            float v = __ldcg(&base[0]);
            #pragma unroll
            for (int c = 1; c < CHUNKS; c++) v = fminf(v, __ldcg(&base[c * SS]));
            v = (v >= 1e30f) ? 0.f : v;
            acc = (double)(v * w);
        }
        part = blockReduceSumD(acc);
    }

    __shared__ bool s_last;
    if (t == 0) g_part[pid] = part;
    __threadfence();
    if (t == 0) {
        unsigned tk = atomicAdd(&g_cnt2, 1u);
        s_last = (tk == (unsigned)(FIN_COUNT - 1));
    }
    __syncthreads();

    if (s_last && t == 0) {
        double p2p = 0.0, prim = 0.0;
        for (int i = 0; i < TAIL_P2P; i++)  p2p  += __ldcg(&g_part[i]);
        for (int i = TAIL_P2P; i < TAIL_BLOCKS; i++) prim += __ldcg(&g_part[i]);
        double embv = __ldcg(&g_emb);
        out[0] = (float)(p2p + prim + embv);
        out[1] = (float)p2p;
        out[2] = (float)prim;
        out[3] = 0.f;
        out[4] = (float)embv;
        // reset all tickets for next graph replay
        g_cnt2 = 0;
        for (int i = 0; i < BB * CHUNKS; i++) g_cntP[i] = 0;
        for (int i = 0; i < BB * MM; i++)     g_cntB[i] = 0;
    }
}

// ---------------- launch ----------------
extern "C" void kernel_launch(void* const* d_in, const int* in_sizes, int n_in,
                              void* d_out, int out_size)
{
    const float* pcl    = (const float*)d_in[0];
    const float* trans  = (const float*)d_in[1];
    const float* rot    = (const float*)d_in[2];
    const float* size   = (const float*)d_in[3];
    const float* shape  = (const float*)d_in[4];
    const float* deform = (const float*)d_in[5];
    const float* prob   = (const float*)d_in[6];
    const float* emb    = (const float*)d_in[7];

    k_all<<<GRID_BLOCKS, 256>>>(pcl, trans, rot, size, shape, deform, prob, emb,
                                (float*)d_out);
}

// round 17
// speedup vs baseline: 1.0752x; 1.0752x over previous
#include <cuda_runtime.h>
#include <math.h>

#define BB 4
#define NN 2048
#define MM 16
#define SS 200
#define PTS 512             // points per producer block
#define CHUNKS (NN / PTS)   // 4

#define PROD_WORK    (BB * MM * CHUNKS)        // 256 merged work blocks
#define PROD_BLOCKS  (PROD_WORK + 1)           // +1 emb block = 257
#define TAIL_P2P     32                        // 32 blocks x 256 points
#define TAIL_PRIM    (BB * MM)                 // 64 blocks, one per (b,m)
#define TAIL_BLOCKS  (TAIL_P2P + TAIL_PRIM)    // 96
#define GRID_BLOCKS  (PROD_BLOCKS + TAIL_BLOCKS)  // 353

typedef unsigned long long ull;

// ---------------- device scratch ----------------
__device__ float    g_dv[BB * NN * MM];                 // TRANSPOSED: [(b*NN+n)*MM + m]
__device__ float    g_dpart[BB * MM * CHUNKS * SS];     // per-chunk partial min-over-n
__device__ double   g_part[TAIL_BLOCKS];                // per-tail-block partial sums
__device__ double   g_emb;
__device__ unsigned g_cnt1;                             // producer ticket (self-resetting)
__device__ unsigned g_cnt2;                             // tail ticket (self-resetting)

// ---------------- f32x2 packed helpers (sm_100) ----------------
__device__ __forceinline__ ull pk2(float lo, float hi) {
    ull r; asm("mov.b64 %0, {%1, %2};" : "=l"(r) : "f"(lo), "f"(hi)); return r;
}
__device__ __forceinline__ ull fma2(ull a, ull b, ull c) {
    ull r; asm("fma.rn.f32x2 %0, %1, %2, %3;" : "=l"(r) : "l"(a), "l"(b), "l"(c)); return r;
}
__device__ __forceinline__ void upk2(ull v, float& lo, float& hi) {
    asm("mov.b64 {%0, %1}, %2;" : "=f"(lo), "=f"(hi) : "l"(v));
}

// fast fexp: sign(x) * (|x|+1e-6)^p via MUFU lg2/ex2
__device__ __forceinline__ float fexp_f(float x, float p) {
    float s = (x > 0.f) ? 1.f : ((x < 0.f) ? -1.f : 0.f);
    return s * __powf(fabsf(x) + 1e-6f, p);
}

__device__ __forceinline__ double blockReduceSumD(double v) {
    __shared__ double sh[32];
    int lane = threadIdx.x & 31, wid = threadIdx.x >> 5;
    #pragma unroll
    for (int o = 16; o; o >>= 1) v += __shfl_down_sync(0xffffffffu, v, o);
    if (lane == 0) sh[wid] = v;
    __syncthreads();
    int nw = (blockDim.x + 31) >> 5;
    v = (threadIdx.x < nw) ? sh[threadIdx.x] : 0.0;
    if (wid == 0) {
        #pragma unroll
        for (int o = 16; o; o >>= 1) v += __shfl_down_sync(0xffffffffu, v, o);
    }
    __syncthreads();
    return v;
}

// argmax_i emb[b][i][m]  (first max on ties)
__device__ __forceinline__ int argmax_col(const float* __restrict__ emb, int b, int m) {
    int j = 0;
    float best = emb[(b * MM + 0) * MM + m];
    #pragma unroll
    for (int i = 1; i < MM; i++) {
        float v = emb[(b * MM + i) * MM + m];
        if (v > best) { best = v; j = i; }
    }
    return j;
}

// ---------------- THE kernel ----------------
__global__ void __launch_bounds__(256, 4) k_all(const float* __restrict__ pcl,
                                                const float* __restrict__ trans,
                                                const float* __restrict__ rot,
                                                const float* __restrict__ size,
                                                const float* __restrict__ shape,
                                                const float* __restrict__ deform,
                                                const float* __restrict__ prob,
                                                const float* __restrict__ emb,
                                                float* __restrict__ out)
{
    int bid = blockIdx.x, t = threadIdx.x;

    // ===================== PRODUCER BLOCKS =====================
    if (bid < PROD_BLOCKS) {
        if (bid == PROD_WORK) {
            // ---- embeddings regularizer ----
            double c1 = 0.0, c2 = 0.0, c3 = 0.0;
            if (t < BB * MM) {
                int bb = t / MM, k = t % MM;
                float s1 = 0.f, s2 = 0.f;
                for (int i = 0; i < MM; i++) {
                    s1 += emb[(bb * MM + i) * MM + k];
                    s2 += emb[(bb * MM + k) * MM + i];
                }
                float d1 = s1 - 1.f, d2 = s2 - 1.f;
                c1 = (double)(d1 * d1);
                c2 = (double)(d2 * d2);
            }
            for (int i = t; i < BB * MM * MM; i += 256) {
                float v = emb[i];
                c3 += (double)(v * (1.f - v));
            }
            double r1 = blockReduceSumD(c1);
            double r2 = blockReduceSumD(c2);
            double r3 = blockReduceSumD(c3);
            if (t == 0) {
                g_emb = r1 / (double)(BB * MM) + 10.0 * r2 / (double)(BB * MM)
                      + r3 / (double)(BB * MM * MM);
                __threadfence();
                atomicAdd(&g_cnt1, 1u);
            }
            return;
        }

        // merged work block: both distance loops for (blkm, chunk of 512 points)
        __shared__ ulonglong2 s_qA[SS / 2], s_qB[SS / 2];     // samples, packed pairs
        __shared__ ulonglong2 s_uA[PTS / 2], s_uB[PTS / 2];   // transformed points, packed
        __shared__ float  s_R[9], s_t[3], s_par[7];

        int blkm  = bid / CHUNKS;
        int chunk = bid % CHUNKS;
        int b     = blkm / MM, m = blkm % MM;

        if (t == 0) {
            int j = argmax_col(emb, b, m);
            const float* q = rot + blkm * 4;
            float w = q[0], x = q[1], y = q[2], z = q[3];
            float inv = rsqrtf(w * w + x * x + y * y + z * z);
            w *= inv; x *= inv; y *= inv; z *= inv;
            s_R[0] = 1.f - 2.f * (y * y + z * z); s_R[1] = 2.f * (x * y - w * z); s_R[2] = 2.f * (x * z + w * y);
            s_R[3] = 2.f * (x * y + w * z); s_R[4] = 1.f - 2.f * (x * x + z * z); s_R[5] = 2.f * (y * z - w * x);
            s_R[6] = 2.f * (x * z - w * y); s_R[7] = 2.f * (y * z + w * x); s_R[8] = 1.f - 2.f * (x * x + y * y);
            s_t[0] = trans[blkm * 3 + 0]; s_t[1] = trans[blkm * 3 + 1]; s_t[2] = trans[blkm * 3 + 2];
            const float* sz3 = size   + (b * MM + j) * 3;
            const float* sh2 = shape  + (b * MM + j) * 2;
            const float* df2 = deform + (b * MM + j) * 2;
            s_par[0] = sh2[0]; s_par[1] = sh2[1];
            s_par[2] = sz3[0]; s_par[3] = sz3[1]; s_par[4] = sz3[2];
            s_par[5] = df2[0]; s_par[6] = df2[1];
        }
        __syncthreads();

        // sample points -> packed smem (t < SS), fast transcendentals
        if (t < SS) {
            float e1 = s_par[0], e2 = s_par[1];
            float sx = s_par[2], sy = s_par[3], szv = s_par[4];
            float dfx = s_par[5], dfy = s_par[6];
            double stepE = (M_PI - 0.1) / (double)(SS - 1);
            double stepO = (2.0 * M_PI - 0.1) / (double)(SS - 1);
            float eta = (float)(-M_PI / 2.0 + 0.05 + t * stepE);
            float omg = (float)(-M_PI + 0.05 + t * stepO);
            float ce = __cosf(eta), se = __sinf(eta);
            float co = __cosf(omg), so = __sinf(omg);
            float fce = fexp_f(ce, e1);
            float x = sx * fce * fexp_f(co, e2);
            float y = sy * fce * fexp_f(so, e2);
            float z = szv * fexp_f(se, e1);
            float fx = dfx / szv * z + 1.f;
            float fy = dfy / szv * z + 1.f;
            float X = x * fx, Y = y * fy, Z = z;
            float W = fmaf(X, X, fmaf(Y, Y, Z * Z));
            int p = t >> 1, h = t & 1;
            float* A = (float*)s_qA;  float* Bf = (float*)s_qB;
            A[4 * p + h]     = X;  A[4 * p + 2 + h] = Y;
            Bf[4 * p + h]    = Z;  Bf[4 * p + 2 + h] = W;
        }

        // transform TWO points per thread (local l0 = t, l1 = t + 256)
        float R0 = s_R[0], R1 = s_R[1], R2 = s_R[2];
        float R3 = s_R[3], R4 = s_R[4], R5 = s_R[5];
        float R6 = s_R[6], R7 = s_R[7], R8 = s_R[8];
        float ux0, uy0, uz0, uw0, ux1, uy1, uz1, uw1;
        {
            int n0 = chunk * PTS + t;
            const float* P0 = pcl + (b * NN + n0) * 3;
            float ax = P0[0] - s_t[0], ay = P0[1] - s_t[1], az = P0[2] - s_t[2];
            ux0 = R0 * ax + R1 * ay + R2 * az;
            uy0 = R3 * ax + R4 * ay + R5 * az;
            uz0 = R6 * ax + R7 * ay + R8 * az;
            uw0 = fmaf(ux0, ux0, fmaf(uy0, uy0, uz0 * uz0));
            const float* P1 = P0 + 256 * 3;
            float bx = P1[0] - s_t[0], by = P1[1] - s_t[1], bz = P1[2] - s_t[2];
            ux1 = R0 * bx + R1 * by + R2 * bz;
            uy1 = R3 * bx + R4 * by + R5 * bz;
            uz1 = R6 * bx + R7 * by + R8 * bz;
            uw1 = fmaf(ux1, ux1, fmaf(uy1, uy1, uz1 * uz1));
            int p = t >> 1, h = t & 1;
            float* A = (float*)s_uA;  float* Bf = (float*)s_uB;
            A[4 * p + h]          = ux0; A[4 * p + 2 + h]        = uy0;
            Bf[4 * p + h]         = uz0; Bf[4 * p + 2 + h]       = uw0;
            A[4 * (p + 128) + h]  = ux1; A[4 * (p + 128) + 2 + h] = uy1;
            Bf[4 * (p + 128) + h] = uz1; Bf[4 * (p + 128) + 2 + h] = uw1;
        }
        __syncthreads();

        // ---------- p2p: min over S for BOTH points (each LDS feeds 2 points) ----------
        {
            ull x0p = pk2(-2.f * ux0, -2.f * ux0);
            ull y0p = pk2(-2.f * uy0, -2.f * uy0);
            ull z0p = pk2(-2.f * uz0, -2.f * uz0);
            ull x1p = pk2(-2.f * ux1, -2.f * ux1);
            ull y1p = pk2(-2.f * uy1, -2.f * uy1);
            ull z1p = pk2(-2.f * uz1, -2.f * uz1);

            float m00 = 3.4e38f, m01 = m00, m02 = m00, m03 = m00;
            float m10 = m00, m11 = m00, m12 = m00, m13 = m00;
            #pragma unroll 5
            for (int p = 0; p < SS / 2; p += 2) {
                ulonglong2 la0 = s_qA[p],     lb0 = s_qB[p];
                ulonglong2 la1 = s_qA[p + 1], lb1 = s_qB[p + 1];
                ull v; float lo, hi;
                v = fma2(la0.x, x0p, fma2(la0.y, y0p, fma2(lb0.x, z0p, lb0.y)));
                upk2(v, lo, hi); m00 = fminf(m00, lo); m01 = fminf(m01, hi);
                v = fma2(la0.x, x1p, fma2(la0.y, y1p, fma2(lb0.x, z1p, lb0.y)));
                upk2(v, lo, hi); m10 = fminf(m10, lo); m11 = fminf(m11, hi);
                v = fma2(la1.x, x0p, fma2(la1.y, y0p, fma2(lb1.x, z0p, lb1.y)));
                upk2(v, lo, hi); m02 = fminf(m02, lo); m03 = fminf(m03, hi);
                v = fma2(la1.x, x1p, fma2(la1.y, y1p, fma2(lb1.x, z1p, lb1.y)));
                upk2(v, lo, hi); m12 = fminf(m12, lo); m13 = fminf(m13, hi);
            }
            int n0 = chunk * PTS + t;
            float d0 = fminf(fminf(m00, m01), fminf(m02, m03)) + uw0;
            float d1 = fminf(fminf(m10, m11), fminf(m12, m13)) + uw1;
            d0 = fmaxf(d0, 0.f);
            d1 = fmaxf(d1, 0.f);
            g_dv[(b * NN + n0) * MM + m]       = d0;
            g_dv[(b * NN + n0 + 256) * MM + m] = d1;
        }

        // ---------- prim: 100 threads x 2 samples over 512 points ----------
        if (t < SS / 2) {
            int p0 = t >> 1, h0 = t & 1;          // sample s0 = t
            int p1 = p0 + 50;                     // sample s1 = t + 100 (same parity)
            const float* A = (const float*)s_qA;  const float* Bf = (const float*)s_qB;
            float qx0 = A[4 * p0 + h0], qy0 = A[4 * p0 + 2 + h0];
            float qz0 = Bf[4 * p0 + h0], qw0 = Bf[4 * p0 + 2 + h0];
            float qx1 = A[4 * p1 + h0], qy1 = A[4 * p1 + 2 + h0];
            float qz1 = Bf[4 * p1 + h0], qw1 = Bf[4 * p1 + 2 + h0];
            ull x0p = pk2(-2.f * qx0, -2.f * qx0);
            ull y0p = pk2(-2.f * qy0, -2.f * qy0);
            ull z0p = pk2(-2.f * qz0, -2.f * qz0);
            ull x1p = pk2(-2.f * qx1, -2.f * qx1);
            ull y1p = pk2(-2.f * qy1, -2.f * qy1);
            ull z1p = pk2(-2.f * qz1, -2.f * qz1);

            float a0 = 3.4e38f, a1 = a0, a2 = a0, a3 = a0;   // s0
            float c0 = a0, c1 = a0, c2 = a0, c3 = a0;        // s1
            #pragma unroll 4
            for (int p = 0; p < PTS / 2; p += 2) {
                ulonglong2 la0 = s_uA[p],     lb0 = s_uB[p];
                ulonglong2 la1 = s_uA[p + 1], lb1 = s_uB[p + 1];
                ull v; float lo, hi;
                v = fma2(la0.x, x0p, fma2(la0.y, y0p, fma2(lb0.x, z0p, lb0.y)));
                upk2(v, lo, hi); a0 = fminf(a0, lo); a1 = fminf(a1, hi);
                v = fma2(la0.x, x1p, fma2(la0.y, y1p, fma2(lb0.x, z1p, lb0.y)));
                upk2(v, lo, hi); c0 = fminf(c0, lo); c1 = fminf(c1, hi);
                v = fma2(la1.x, x0p, fma2(la1.y, y0p, fma2(lb1.x, z0p, lb1.y)));
                upk2(v, lo, hi); a2 = fminf(a2, lo); a3 = fminf(a3, hi);
                v = fma2(la1.x, x1p, fma2(la1.y, y1p, fma2(lb1.x, z1p, lb1.y)));
                upk2(v, lo, hi); c2 = fminf(c2, lo); c3 = fminf(c3, hi);
            }
            float d0 = fminf(fminf(a0, a1), fminf(a2, a3)) + qw0;
            float d1 = fminf(fminf(c0, c1), fminf(c2, c3)) + qw1;
            d0 = fmaxf(d0, 0.f);
            d1 = fmaxf(d1, 0.f);
            float* dst = g_dpart + (blkm * CHUNKS + chunk) * SS;
            dst[t]       = d0;
            dst[t + 100] = d1;
        }

        __syncthreads();
        if (t == 0) {
            __threadfence();
            atomicAdd(&g_cnt1, 1u);
        }
        return;
    }

    // ===================== TAIL BLOCKS (spin until producers done) =====================
    if (t == 0) {
        volatile unsigned* c = &g_cnt1;
        while (*c < (unsigned)PROD_BLOCKS) __nanosleep(64);
    }
    __syncthreads();
    __threadfence();   // order subsequent reads after observed release

    int pid = bid - PROD_BLOCKS;   // 0..95
    double part = 0.0;

    if (pid < TAIL_P2P) {
        // ---- p2p weighting: 32 blocks x 256 points ----
        __shared__ float s_p[MM];
        int b = pid / 8, c8 = pid % 8;
        if (t < MM) s_p[t] = prob[b * MM + t];
        __syncthreads();

        int n = c8 * 256 + t;
        const float4* dvp = (const float4*)&g_dv[(b * NN + n) * MM];
        float dv[MM], pv[MM];
        float4 d0 = __ldcg(&dvp[0]), d1 = __ldcg(&dvp[1]);
        float4 d2 = __ldcg(&dvp[2]), d3 = __ldcg(&dvp[3]);
        ((float4*)dv)[0] = d0; ((float4*)dv)[1] = d1;
        ((float4*)dv)[2] = d2; ((float4*)dv)[3] = d3;
        #pragma unroll
        for (int mm = 0; mm < MM; mm++) pv[mm] = s_p[mm];

        float acc = 0.f;
        #pragma unroll
        for (int mm = 0; mm < MM; mm++) {
            float w = pv[mm];
            #pragma unroll
            for (int j = 0; j < MM; j++) {
                if (j == mm) continue;
                bool before = (dv[j] < dv[mm]) || (dv[j] == dv[mm] && j < mm);
                w *= before ? (1.f - pv[j]) : 1.f;
            }
            acc = fmaf(dv[mm], w, acc);
        }
        part = blockReduceSumD((double)acc) / (double)(BB * NN);
    } else {
        // ---- prim reduction: one block per (b,m) ----
        int blkm = pid - TAIL_P2P;
        int b = blkm / MM;
        __shared__ float s_a[MM];
        __shared__ float s_w[1];

        if (t < MM) {
            int j = argmax_col(emb, b, t);
            const float* sz3 = size + (b * MM + j) * 3;
            float a0 = sz3[0], a1 = sz3[1], a2 = sz3[2];
            float ar = powf(a0 * a1, 1.6f) / 3.f + powf(a0 * a2, 1.6f) / 3.f + powf(a1 * a2, 1.6f) / 3.f;
            s_a[t] = 4.f * (float)M_PI * powf(ar, 0.625f);
        }
        __syncthreads();
        if (t == 0) {
            float sa = 0.f;
            #pragma unroll
            for (int mm = 0; mm < MM; mm++) sa += s_a[mm];
            s_w[0] = s_a[blkm % MM] / sa / (float)(SS * BB);
        }
        __syncthreads();
        float w = s_w[0];

        double acc = 0.0;
        if (t < SS) {
            const float* base = g_dpart + (blkm * CHUNKS) * SS + t;
            float v = __ldcg(&base[0]);
            #pragma unroll
            for (int c = 1; c < CHUNKS; c++) v = fminf(v, __ldcg(&base[c * SS]));
            v = (v >= 1e30f) ? 0.f : v;
            acc = (double)(v * w);
        }
        part = blockReduceSumD(acc);
    }

    __shared__ bool s_last;
    if (t == 0) g_part[pid] = part;
    __threadfence();
    if (t == 0) {
        unsigned tk = atomicAdd(&g_cnt2, 1u);
        s_last = (tk == (unsigned)(TAIL_BLOCKS - 1));
    }
    __syncthreads();

    if (s_last && t == 0) {
        double p2p = 0.0, prim = 0.0;
        for (int i = 0; i < TAIL_P2P; i++)  p2p  += __ldcg(&g_part[i]);
        for (int i = TAIL_P2P; i < TAIL_BLOCKS; i++) prim += __ldcg(&g_part[i]);
        double embv = __ldcg(&g_emb);
        out[0] = (float)(p2p + prim + embv);
        out[1] = (float)p2p;
        out[2] = (float)prim;
        out[3] = 0.f;
        out[4] = (float)embv;
        g_cnt1 = 0;   // reset for next graph replay
        g_cnt2 = 0;
    }
}

// ---------------- launch ----------------
extern "C" void kernel_launch(void* const* d_in, const int* in_sizes, int n_in,
                              void* d_out, int out_size)
{
    const float* pcl    = (const float*)d_in[0];
    const float* trans  = (const float*)d_in[1];
    const float* rot    = (const float*)d_in[2];
    const float* size   = (const float*)d_in[3];
    const float* shape  = (const float*)d_in[4];
    const float* deform = (const float*)d_in[5];
    const float* prob   = (const float*)d_in[6];
    const float* emb    = (const float*)d_in[7];

    k_all<<<GRID_BLOCKS, 256>>>(pcl, trans, rot, size, shape, deform, prob, emb,
                                (float*)d_out);
}